// round 1
// baseline (speedup 1.0000x reference)
#include <cuda_runtime.h>
#include <cuda_bf16.h>
#include <math.h>

// Monomial layout constants (D = 64, degrees 0..4)
//   off0=0 (1), off1=1 (64), off2=65 (2080), off3=2145 (45760), off4=47905 (766480)
// Total F = 814385.
#define NT 128
#define N_M4_TASKS 2080          // one task per leading (i,j) pair, i<=j
#define N_TASKS (N_M4_TASKS + 64 + 1 + 1)   // + deg3 per-i + deg2 + deg1/0 = 2146

__device__ float g_partials[N_TASKS];

__device__ __forceinline__ int C2i(int n) { return (n >= 2) ? n * (n - 1) / 2 : 0; }
__device__ __forceinline__ int C3i(int n) { return (n >= 3) ? n * (n - 1) * (n - 2) / 6 : 0; }
__device__ __forceinline__ int C4i(int n) { return (n >= 4) ? n * (n - 1) * (n - 2) * (n - 3) / 24 : 0; }

// Unrank flat index p in a "lower triangle" with row sizes n, n-1, ..., 1.
// Returns row r (0-based) and column offset c within the row.
// S(r) = r*n - r*(r-1)/2 is the start of row r.
__device__ __forceinline__ void unrank_tri(int n, int p, int& r_out, int& c_out) {
    float b = 2.0f * (float)n + 1.0f;
    float disc = b * b - 8.0f * (float)p;
    int r = (int)(0.5f * (b - sqrtf(disc)));
    if (r < 0) r = 0;
    if (r > n - 1) r = n - 1;
    // fixup (float estimate can be off by 1 at row boundaries)
    while (r + 1 <= n - 1 && ((r + 1) * n - (r + 1) * r / 2) <= p) r++;
    while (r > 0 && (r * n - r * (r - 1) / 2) > p) r--;
    r_out = r;
    c_out = p - (r * n - r * (r - 1) / 2);
}

__global__ void __launch_bounds__(NT)
poly_partial_kernel(const float* __restrict__ x,
                    const float* __restrict__ w,
                    const float* __restrict__ alphas) {
    __shared__ float sx[64];
    __shared__ float red[NT];
    const int tid = threadIdx.x;
    if (tid < 64) sx[tid] = x[tid];
    __syncthreads();

    const int task = blockIdx.x;
    float acc = 0.0f;
    float scale = 0.0f;
    float extra = 0.0f;

    if (task < N_M4_TASKS) {
        // ---- degree 4: task -> leading pair (i, j), i <= j ----
        // base2(i) = 2080 - C2(65-i) = # pairs with first index < i
        int i = 0;
        while (i < 63 && (2080 - C2i(64 - i)) <= task) i++;
        const int j = i + (task - (2080 - C2i(65 - i)));
        // w base: off4 + (# deg4 tuples with first < i) + (# with first==i, second < j)
        const int base = 47905 + (C4i(67) - C4i(67 - i)) + (C3i(66 - i) - C3i(66 - j));
        const int n = 64 - j;                 // inner triangle over (k, l), j<=k<=l<64
        const int count = n * (n + 1) / 2;    // contiguous in w -> coalesced
        scale = alphas[4] * sx[i] * sx[j];
        for (int p = tid; p < count; p += NT) {
            int r, c;
            unrank_tri(n, p, r, c);
            const int k = j + r;
            const int l = k + c;
            acc += w[base + p] * sx[k] * sx[l];
        }
    } else if (task < N_M4_TASKS + 64) {
        // ---- degree 3: task -> leading index i ----
        const int i = task - N_M4_TASKS;
        const int base = 2145 + (C3i(66) - C3i(66 - i));
        const int n = 64 - i;                 // triangle over (j, k), i<=j<=k<64
        const int count = n * (n + 1) / 2;
        scale = alphas[3] * sx[i];
        for (int p = tid; p < count; p += NT) {
            int r, c;
            unrank_tri(n, p, r, c);
            const int jj = i + r;
            const int k = jj + c;
            acc += w[base + p] * sx[jj] * sx[k];
        }
    } else if (task == N_M4_TASKS + 64) {
        // ---- degree 2: full triangle over (i, j) ----
        const int base = 65;
        const int n = 64;
        const int count = 2080;
        scale = alphas[2];
        for (int p = tid; p < count; p += NT) {
            int r, c;
            unrank_tri(n, p, r, c);
            acc += w[base + p] * sx[r] * sx[r + c];
        }
    } else {
        // ---- degree 1 + degree 0 ----
        scale = alphas[1];
        if (tid < 64) acc = w[1 + tid] * sx[tid];
        extra = alphas[0] * w[0];
    }

    // deterministic shared-memory tree reduction
    red[tid] = acc;
    __syncthreads();
    #pragma unroll
    for (int s = NT / 2; s > 0; s >>= 1) {
        if (tid < s) red[tid] += red[tid + s];
        __syncthreads();
    }
    if (tid == 0) g_partials[task] = red[0] * scale + extra;
}

__global__ void __launch_bounds__(256)
poly_reduce_kernel(float* __restrict__ out) {
    __shared__ float red[256];
    const int tid = threadIdx.x;
    float acc = 0.0f;
    for (int i = tid; i < N_TASKS; i += 256) acc += g_partials[i];
    red[tid] = acc;
    __syncthreads();
    #pragma unroll
    for (int s = 128; s > 0; s >>= 1) {
        if (tid < s) red[tid] += red[tid + s];
        __syncthreads();
    }
    if (tid == 0) {
        const float f = red[0];
        out[0] = 1.0f / (1.0f + expf(-f));
    }
}

extern "C" void kernel_launch(void* const* d_in, const int* in_sizes, int n_in,
                              void* d_out, int out_size) {
    // metadata order: x [64] f32, w [814385] f32, alphas [5] f32,
    //                 E [814385*64] i32 (UNUSED), ord_ids [814385] i32 (UNUSED)
    const float* x      = (const float*)d_in[0];
    const float* w      = (const float*)d_in[1];
    const float* alphas = (const float*)d_in[2];
    float* out = (float*)d_out;

    poly_partial_kernel<<<N_TASKS, NT>>>(x, w, alphas);
    poly_reduce_kernel<<<1, 256>>>(out);
}